// round 15
// baseline (speedup 1.0000x reference)
#include <cuda_runtime.h>
#include <cuda_bf16.h>
#include <cstdint>

#define N_NODES 2048
#define NQ (N_NODES / 4)          // 512 float4 per row
#define EPS 0.01f
#define THREADS 256
#define CHUNKS 74                 // per batch -> 8*74 = 592 CTAs = 148 SMs * 4

__device__ unsigned long long g_combined = 0ULL;  // [arrivals:32 | count:32]

__device__ __forceinline__ int pair4(const float4 w, const float pi, const float4 pj)
{
    int c = 0;
    c += (w.x == 1.0f) & (fabsf(pi - pj.x) < EPS);
    c += (w.y == 1.0f) & (fabsf(pi - pj.y) < EPS);
    c += (w.z == 1.0f) & (fabsf(pi - pj.z) < EPS);
    c += (w.w == 1.0f) & (fabsf(pi - pj.w) < EPS);
    return c;
}

__global__ void __launch_bounds__(THREADS, 4) count_kernel(
    const float* __restrict__ W, const float* __restrict__ pred,
    float* __restrict__ out, int nblocks)
{
    const int bid = blockIdx.x;
    const int b   = bid / CHUNKS;
    const int c   = bid % CHUNKS;
    const int start = (c * N_NODES) / CHUNKS;
    const int end   = ((c + 1) * N_NODES) / CHUNKS;   // 27 or 28 rows, same batch
    const int tid = threadIdx.x;

    const float* predb = pred + ((size_t)b << 11);
    const float4* Wt = (const float4*)(W + (size_t)(2 * b + 1) * (size_t)N_NODES * N_NODES)
                       + (size_t)start * NQ + tid;

    // --- prologue: start the W stream FIRST (DRAM busy from cycle ~0) ---
    float4 w0[2], w1[2];
    float  pi[2];
    w0[0] = __ldcs(Wt);
    w1[0] = __ldcs(Wt + THREADS);

    // per-thread fixed column groups (L2-hot after first CTA of each batch)
    const float4 pj0 = __ldg((const float4*)predb + tid);
    const float4 pj1 = __ldg((const float4*)predb + tid + THREADS);
    pi[0] = __ldg(predb + start);

    int cnt = 0;
    int p = 0;
    #pragma unroll 2
    for (int r = start; r < end; ++r) {
        const int nxt = p ^ 1;
        if (r + 1 < end) {
            const float4* wn = Wt + (size_t)(r + 1 - start) * NQ;
            w0[nxt] = __ldcs(wn);
            w1[nxt] = __ldcs(wn + THREADS);
            pi[nxt] = __ldg(predb + r + 1);
        }
        cnt += pair4(w0[p], pi[p], pj0);
        cnt += pair4(w1[p], pi[p], pj1);
        p = nxt;
    }

    // block reduce
    #pragma unroll
    for (int o = 16; o > 0; o >>= 1)
        cnt += __shfl_xor_sync(0xffffffffu, cnt, o);

    __shared__ int warpsum[THREADS / 32];
    if ((tid & 31) == 0)
        warpsum[tid >> 5] = cnt;
    __syncthreads();

    if (tid == 0) {
        int v = 0;
        #pragma unroll
        for (int i = 0; i < THREADS / 32; ++i)
            v += warpsum[i];
        // one packed RMW: arrivals in high 32, count in low 32. The RMW total
        // order guarantees the last arriver's returned value holds the full
        // partial sum of all other CTAs — no fence, no partials array.
        unsigned long long old =
            atomicAdd(&g_combined, (1ULL << 32) | (unsigned long long)(unsigned)v);
        if ((unsigned)(old >> 32) == (unsigned)(nblocks - 1)) {
            const unsigned total = (unsigned)old + (unsigned)v;
            out[0] = (float)total;
            g_combined = 0ULL;   // reset for next graph replay (deterministic)
        }
    }
}

extern "C" void kernel_launch(void* const* d_in, const int* in_sizes, int n_in,
                              void* d_out, int out_size)
{
    const float* W    = (const float*)d_in[0];
    const float* pred = (const float*)d_in[1];
    float* out = (float*)d_out;

    const int B = in_sizes[1] / N_NODES;
    const int nblocks = B * CHUNKS;     // 592
    count_kernel<<<nblocks, THREADS>>>(W, pred, out, nblocks);
}

// round 16
// speedup vs baseline: 1.0497x; 1.0497x over previous
#include <cuda_runtime.h>
#include <cuda_bf16.h>
#include <cstdint>

#define N_NODES 2048
#define NQ (N_NODES / 4)          // 512 float4 per row
#define EPS 0.01f
#define THREADS 256
#define CHUNKS 74                 // per batch -> 8*74 = 592 CTAs = 148 SMs * 4

__device__ unsigned long long g_combined = 0ULL;  // [arrivals:32 | count:32]

__device__ __forceinline__ int pair4(const float4 w, const float pi, const float4 pj)
{
    int c = 0;
    c += (w.x == 1.0f) & (fabsf(pi - pj.x) < EPS);
    c += (w.y == 1.0f) & (fabsf(pi - pj.y) < EPS);
    c += (w.z == 1.0f) & (fabsf(pi - pj.z) < EPS);
    c += (w.w == 1.0f) & (fabsf(pi - pj.w) < EPS);
    return c;
}

__global__ void __launch_bounds__(THREADS, 4) count_kernel(
    const float* __restrict__ W, const float* __restrict__ pred,
    float* __restrict__ out, int nblocks)
{
    const int bid = blockIdx.x;
    const int b   = bid / CHUNKS;
    const int c   = bid % CHUNKS;
    const int start = (c * N_NODES) / CHUNKS;
    const int end   = ((c + 1) * N_NODES) / CHUNKS;   // n = 27 or 28 rows, same batch
    const int n = end - start;
    const int tid = threadIdx.x;

    const float* predb = pred + ((size_t)b << 11);
    const float4* Wt = (const float4*)(W + (size_t)(2 * b + 1) * (size_t)N_NODES * N_NODES)
                       + (size_t)start * NQ + tid;

    // --- prologue: start the W stream FIRST (DRAM busy from cycle ~0) ---
    float4 w0[2], w1[2];
    float  pi[2];
    w0[0] = __ldcs(Wt);
    w1[0] = __ldcs(Wt + THREADS);

    // per-thread fixed column groups (L2-hot after first CTA of each batch)
    const float4 pj0 = __ldg((const float4*)predb + tid);
    const float4 pj1 = __ldg((const float4*)predb + tid + THREADS);
    pi[0] = __ldg(predb + start);

    int cnt = 0;
    int p = 0;
    // steady state: branch-free loads (last iteration peeled)
    #pragma unroll 2
    for (int r = 0; r < n - 1; ++r) {
        const int nxt = p ^ 1;
        const float4* wn = Wt + (size_t)(r + 1) * NQ;
        w0[nxt] = __ldcs(wn);
        w1[nxt] = __ldcs(wn + THREADS);
        pi[nxt] = __ldg(predb + start + r + 1);
        cnt += pair4(w0[p], pi[p], pj0);
        cnt += pair4(w1[p], pi[p], pj1);
        p = nxt;
    }
    // epilogue: final row
    cnt += pair4(w0[p], pi[p], pj0);
    cnt += pair4(w1[p], pi[p], pj1);

    // block reduce
    #pragma unroll
    for (int o = 16; o > 0; o >>= 1)
        cnt += __shfl_xor_sync(0xffffffffu, cnt, o);

    __shared__ int warpsum[THREADS / 32];
    if ((tid & 31) == 0)
        warpsum[tid >> 5] = cnt;
    __syncthreads();

    if (tid == 0) {
        int v = 0;
        #pragma unroll
        for (int i = 0; i < THREADS / 32; ++i)
            v += warpsum[i];
        // one packed RMW: arrivals in high 32, count in low 32. The RMW total
        // order guarantees the last arriver's returned value holds the full
        // partial sum of all other CTAs — no fence, no partials array.
        unsigned long long old =
            atomicAdd(&g_combined, (1ULL << 32) | (unsigned long long)(unsigned)v);
        if ((unsigned)(old >> 32) == (unsigned)(nblocks - 1)) {
            const unsigned total = (unsigned)old + (unsigned)v;
            out[0] = (float)total;
            g_combined = 0ULL;   // reset for next graph replay (deterministic)
        }
    }
}

extern "C" void kernel_launch(void* const* d_in, const int* in_sizes, int n_in,
                              void* d_out, int out_size)
{
    const float* W    = (const float*)d_in[0];
    const float* pred = (const float*)d_in[1];
    float* out = (float*)d_out;

    const int B = in_sizes[1] / N_NODES;
    const int nblocks = B * CHUNKS;     // 592
    count_kernel<<<nblocks, THREADS>>>(W, pred, out, nblocks);
}